// round 1
// baseline (speedup 1.0000x reference)
#include <cuda_runtime.h>
#include <math.h>

// Problem constants
#define SDIM   256
#define MDIM   64
#define NSTUDY 1000

// Per-group precomputed constants
struct GConst {
    float k;      // d/c = sum_m2 / (v*sum_m)
    float logk;   // log(d/c)
    float r;      // v*sum_m^2/sum_m2 (scalar!)
    float T1, T2, T3; // lgamma(y+r)-lgamma(y+1)-lgamma(r) for y=1,2,3
};

__device__ GConst g_c[2];
__device__ double g_sum;

// ---------------------------------------------------------------------------
// Kernel 0: compute per-group scalars from moderators, zero the accumulator.
// One block, 256 threads. Tiny (1000x64 matvec x2).
// ---------------------------------------------------------------------------
__global__ void setup_kernel(const float* __restrict__ mod0,
                             const float* __restrict__ mod1,
                             const float* __restrict__ wm,
                             const float* __restrict__ ods)
{
    __shared__ float swm[MDIM];
    __shared__ double rbuf[256];
    const int tid = threadIdx.x;
    if (tid < MDIM) swm[tid] = wm[tid];
    __syncthreads();

    double m0 = 0.0, m20 = 0.0, m1 = 0.0, m21 = 0.0;
    for (int s = tid; s < NSTUDY; s += 256) {
        const float* r0 = mod0 + (size_t)s * MDIM;
        const float* r1 = mod1 + (size_t)s * MDIM;
        float d0 = 0.f, d1 = 0.f;
        #pragma unroll 8
        for (int j = 0; j < MDIM; ++j) {
            d0 = fmaf(r0[j], swm[j], d0);
            d1 = fmaf(r1[j], swm[j], d1);
        }
        double e0 = exp((double)d0), e1 = exp((double)d1);
        m0 += e0; m20 += e0 * e0;
        m1 += e1; m21 += e1 * e1;
    }

    // 4 block reductions
    double vals[4] = {m0, m20, m1, m21};
    double out[4];
    for (int q = 0; q < 4; ++q) {
        rbuf[tid] = vals[q];
        __syncthreads();
        for (int s = 128; s > 0; s >>= 1) {
            if (tid < s) rbuf[tid] += rbuf[tid + s];
            __syncthreads();
        }
        out[q] = rbuf[0];
        __syncthreads();
    }

    if (tid == 0) {
        double sm[2]  = {out[0], out[2]};
        double sm2[2] = {out[1], out[3]};
        for (int g = 0; g < 2; ++g) {
            double s  = (double)ods[g];
            double v  = 1.0 / (s * s);
            double c  = v * sm[g];
            double d  = sm2[g];
            double r  = v * sm[g] * sm[g] / sm2[g];
            double k  = d / c;
            double T1 = log(r);
            double T2 = T1 + log(r + 1.0) - log(2.0);
            double T3 = T2 + log(r + 2.0) - log(3.0);
            g_c[g].k = (float)k;
            g_c[g].logk = (float)log(k);
            g_c[g].r = (float)r;
            g_c[g].T1 = (float)T1;
            g_c[g].T2 = (float)T2;
            g_c[g].T3 = (float)T3;
        }
        g_sum = 0.0;  // reset every graph replay
    }
}

// Per-voxel, per-group log-likelihood contribution.
// t = k*exp(dot);  log(1-p) = -log1p(t);  log(p) = dot + logk - log1p(t)
// term = -(r+y)*log1p(t) + y*(dot + logk) + T[y]
__device__ __forceinline__ float group_term(const GConst gc, float dot, float y)
{
    float t  = gc.k * expf(dot);
    float l1 = log1pf(t);
    int iy = (int)y;
    float T = (iy == 1) ? gc.T1 : (iy == 2) ? gc.T2 : (iy == 3) ? gc.T3 : 0.0f;
    return fmaf(-(gc.r + y), l1, fmaf(y, gc.logk + dot, T));
}

// ---------------------------------------------------------------------------
// Kernel 1: main streaming kernel. Warp per voxel, grid-stride, 2x unroll.
// ---------------------------------------------------------------------------
__global__ void __launch_bounds__(256)
nb_main_kernel(const float* __restrict__ X,
               const float* __restrict__ y0,
               const float* __restrict__ y1,
               const float* __restrict__ W,
               int V)
{
    const int lane   = threadIdx.x & 31;
    const int widb   = threadIdx.x >> 5;
    const int nwb    = blockDim.x >> 5;
    const int gwarp  = blockIdx.x * nwb + widb;
    const int nwarps = gridDim.x * nwb;

    // Per-lane weight slices (elements 4*lane..4*lane+3 and 128+4*lane..)
    const float4* W4 = (const float4*)W;
    const float4 w0a = W4[lane],      w0b = W4[lane + 32];
    const float4 w1a = W4[64 + lane], w1b = W4[96 + lane];

    const GConst c0 = g_c[0];
    const GConst c1 = g_c[1];

    double acc = 0.0;

    int v = gwarp;
    // 2x unrolled main loop for load-level parallelism
    for (; v + nwarps < V; v += 2 * nwarps) {
        const int v2 = v + nwarps;
        const float4* xr1 = (const float4*)(X + (size_t)v  * SDIM);
        const float4* xr2 = (const float4*)(X + (size_t)v2 * SDIM);
        float4 a1 = xr1[lane], b1 = xr1[lane + 32];
        float4 a2 = xr2[lane], b2 = xr2[lane + 32];

        float p0 = a1.x*w0a.x + a1.y*w0a.y + a1.z*w0a.z + a1.w*w0a.w
                 + b1.x*w0b.x + b1.y*w0b.y + b1.z*w0b.z + b1.w*w0b.w;
        float p1 = a1.x*w1a.x + a1.y*w1a.y + a1.z*w1a.z + a1.w*w1a.w
                 + b1.x*w1b.x + b1.y*w1b.y + b1.z*w1b.z + b1.w*w1b.w;
        float q0 = a2.x*w0a.x + a2.y*w0a.y + a2.z*w0a.z + a2.w*w0a.w
                 + b2.x*w0b.x + b2.y*w0b.y + b2.z*w0b.z + b2.w*w0b.w;
        float q1 = a2.x*w1a.x + a2.y*w1a.y + a2.z*w1a.z + a2.w*w1a.w
                 + b2.x*w1b.x + b2.y*w1b.y + b2.z*w1b.z + b2.w*w1b.w;

        #pragma unroll
        for (int off = 16; off > 0; off >>= 1) {
            p0 += __shfl_xor_sync(0xffffffff, p0, off);
            p1 += __shfl_xor_sync(0xffffffff, p1, off);
            q0 += __shfl_xor_sync(0xffffffff, q0, off);
            q1 += __shfl_xor_sync(0xffffffff, q1, off);
        }

        if (lane == 0) {
            float ya1 = y0[v],  yb1 = y1[v];
            float ya2 = y0[v2], yb2 = y1[v2];
            float s1 = group_term(c0, p0, ya1) + group_term(c1, p1, yb1);
            float s2 = group_term(c0, q0, ya2) + group_term(c1, q1, yb2);
            acc += (double)s1 + (double)s2;
        }
    }
    // remainder
    if (v < V) {
        const float4* xr1 = (const float4*)(X + (size_t)v * SDIM);
        float4 a1 = xr1[lane], b1 = xr1[lane + 32];
        float p0 = a1.x*w0a.x + a1.y*w0a.y + a1.z*w0a.z + a1.w*w0a.w
                 + b1.x*w0b.x + b1.y*w0b.y + b1.z*w0b.z + b1.w*w0b.w;
        float p1 = a1.x*w1a.x + a1.y*w1a.y + a1.z*w1a.z + a1.w*w1a.w
                 + b1.x*w1b.x + b1.y*w1b.y + b1.z*w1b.z + b1.w*w1b.w;
        #pragma unroll
        for (int off = 16; off > 0; off >>= 1) {
            p0 += __shfl_xor_sync(0xffffffff, p0, off);
            p1 += __shfl_xor_sync(0xffffffff, p1, off);
        }
        if (lane == 0) {
            float ya1 = y0[v], yb1 = y1[v];
            acc += (double)(group_term(c0, p0, ya1) + group_term(c1, p1, yb1));
        }
    }

    // block reduce (lane0 of each warp holds a partial), one atomic per block
    __shared__ double sred[8];
    if (lane == 0) sred[widb] = acc;
    __syncthreads();
    if (threadIdx.x == 0) {
        double t = 0.0;
        for (int i = 0; i < nwb; ++i) t += sred[i];
        atomicAdd(&g_sum, t);
    }
}

// ---------------------------------------------------------------------------
// Kernel 2: write the negated sum as float scalar.
// ---------------------------------------------------------------------------
__global__ void finalize_kernel(float* out)
{
    out[0] = (float)(-g_sum);
}

extern "C" void kernel_launch(void* const* d_in, const int* in_sizes, int n_in,
                              void* d_out, int out_size)
{
    const float* X    = (const float*)d_in[0]; // [V,256]
    const float* mod0 = (const float*)d_in[1]; // [1000,64]
    const float* mod1 = (const float*)d_in[2];
    const float* y0   = (const float*)d_in[3]; // [V,1]
    const float* y1   = (const float*)d_in[4];
    const float* W    = (const float*)d_in[5]; // [2,256]
    const float* wm   = (const float*)d_in[6]; // [1,64]
    const float* ods  = (const float*)d_in[7]; // [2]
    float* out = (float*)d_out;

    const int V = in_sizes[0] / SDIM;

    setup_kernel<<<1, 256>>>(mod0, mod1, wm, ods);
    nb_main_kernel<<<1184, 256>>>(X, y0, y1, W, V);
    finalize_kernel<<<1, 1>>>(out);
}

// round 2
// speedup vs baseline: 1.3571x; 1.3571x over previous
#include <cuda_runtime.h>
#include <math.h>

#define SDIM   256
#define MDIM   64

// Per-group precomputed constants
struct GConst {
    float k;      // sum_m2 / (v*sum_m)
    float logk;
    float r;      // v*sum_m^2/sum_m2 (per-group scalar)
    float T1, T2, T3; // lgamma(y+r)-lgamma(y+1)-lgamma(r) for y=1,2,3
};

__device__ GConst g_c[2];
__device__ double g_sum;

// ---------------------------------------------------------------------------
// Kernel 0: per-group scalars. 1 block, 1024 threads, thread-per-study,
// float math + MUFU expf; doubles only for accumulation (HW DADD).
// ---------------------------------------------------------------------------
__global__ void __launch_bounds__(1024)
setup_kernel(const float* __restrict__ mod0,
             const float* __restrict__ mod1,
             const float* __restrict__ wm,
             const float* __restrict__ ods,
             int nstudy)
{
    __shared__ float swm[MDIM];
    __shared__ double red[1024];
    const int tid = threadIdx.x;
    if (tid < MDIM) swm[tid] = wm[tid];
    __syncthreads();

    double m0 = 0.0, m20 = 0.0, m1 = 0.0, m21 = 0.0;
    for (int s = tid; s < nstudy; s += 1024) {
        const float4* r0 = (const float4*)(mod0 + (size_t)s * MDIM);
        const float4* r1 = (const float4*)(mod1 + (size_t)s * MDIM);
        float d0 = 0.f, d1 = 0.f;
        #pragma unroll
        for (int j = 0; j < MDIM / 4; ++j) {
            float4 a = r0[j], b = r1[j];
            const float4 w = ((const float4*)swm)[j];
            d0 += a.x*w.x + a.y*w.y + a.z*w.z + a.w*w.w;
            d1 += b.x*w.x + b.y*w.y + b.z*w.z + b.w*w.w;
        }
        float e0 = expf(d0), e1 = expf(d1);
        m0  += (double)e0;  m20 += (double)e0 * (double)e0;
        m1  += (double)e1;  m21 += (double)e1 * (double)e1;
    }

    double vals[4] = {m0, m20, m1, m21};
    double out[4];
    #pragma unroll
    for (int q = 0; q < 4; ++q) {
        red[tid] = vals[q];
        __syncthreads();
        for (int s = 512; s > 0; s >>= 1) {
            if (tid < s) red[tid] += red[tid + s];
            __syncthreads();
        }
        out[q] = red[0];
        __syncthreads();
    }

    if (tid == 0) {
        double sm[2]  = {out[0], out[2]};
        double sm2[2] = {out[1], out[3]};
        #pragma unroll
        for (int g = 0; g < 2; ++g) {
            float  s  = ods[g];
            double v  = 1.0 / ((double)s * (double)s);
            double r  = v * sm[g] * sm[g] / sm2[g];
            double k  = sm2[g] / (v * sm[g]);
            float rf = (float)r;
            float T1 = logf(rf);
            float T2 = T1 + logf(rf + 1.0f) - 0.6931471805599453f;   // -log2
            float T3 = T2 + logf(rf + 2.0f) - 1.0986122886681098f;   // -log3
            g_c[g].k = (float)k;
            g_c[g].logk = logf((float)k);
            g_c[g].r = rf;
            g_c[g].T1 = T1;
            g_c[g].T2 = T2;
            g_c[g].T3 = T3;
        }
        g_sum = 0.0;
    }
}

// term = -(r+y)*log1p(t) + y*(dot + logk) + T[y],  t = k*exp(dot)
__device__ __forceinline__ float group_term(const GConst gc, float dot, float y)
{
    float t  = gc.k * __expf(dot);
    float l1 = log1pf(t);
    int iy = (int)y;
    float T = (iy == 1) ? gc.T1 : (iy == 2) ? gc.T2 : (iy == 3) ? gc.T3 : 0.0f;
    return fmaf(-(gc.r + y), l1, fmaf(y, gc.logk + dot, T));
}

__device__ __forceinline__ float2 dots_for_row(const float4 a, const float4 b,
                                               const float4 w0a, const float4 w0b,
                                               const float4 w1a, const float4 w1b)
{
    float p0 = a.x*w0a.x + a.y*w0a.y + a.z*w0a.z + a.w*w0a.w
             + b.x*w0b.x + b.y*w0b.y + b.z*w0b.z + b.w*w0b.w;
    float p1 = a.x*w1a.x + a.y*w1a.y + a.z*w1a.z + a.w*w1a.w
             + b.x*w1b.x + b.y*w1b.y + b.z*w1b.z + b.w*w1b.w;
    return make_float2(p0, p1);
}

// ---------------------------------------------------------------------------
// Kernel 1: streaming kernel. Warp per voxel, 4x unroll, __ldcs streaming.
// ---------------------------------------------------------------------------
__global__ void __launch_bounds__(256)
nb_main_kernel(const float* __restrict__ X,
               const float* __restrict__ y0,
               const float* __restrict__ y1,
               const float* __restrict__ W,
               int V)
{
    const int lane   = threadIdx.x & 31;
    const int widb   = threadIdx.x >> 5;
    const int nwb    = blockDim.x >> 5;
    const int gwarp  = blockIdx.x * nwb + widb;
    const int nwarps = gridDim.x * nwb;

    const float4* W4 = (const float4*)W;
    const float4 w0a = W4[lane],      w0b = W4[lane + 32];
    const float4 w1a = W4[64 + lane], w1b = W4[96 + lane];

    const GConst c0 = g_c[0];
    const GConst c1 = g_c[1];

    double acc = 0.0;

    int v = gwarp;
    const int step = nwarps;
    // 4x unrolled: 8 front-batched LDG.128 per thread
    for (; v + 3 * step < V; v += 4 * step) {
        const int v1 = v + step, v2 = v + 2 * step, v3 = v + 3 * step;
        const float4* x0 = (const float4*)(X + (size_t)v  * SDIM);
        const float4* x1 = (const float4*)(X + (size_t)v1 * SDIM);
        const float4* x2 = (const float4*)(X + (size_t)v2 * SDIM);
        const float4* x3 = (const float4*)(X + (size_t)v3 * SDIM);

        float4 a0 = __ldcs(x0 + lane), b0 = __ldcs(x0 + lane + 32);
        float4 a1 = __ldcs(x1 + lane), b1 = __ldcs(x1 + lane + 32);
        float4 a2 = __ldcs(x2 + lane), b2 = __ldcs(x2 + lane + 32);
        float4 a3 = __ldcs(x3 + lane), b3 = __ldcs(x3 + lane + 32);

        float2 d0 = dots_for_row(a0, b0, w0a, w0b, w1a, w1b);
        float2 d1 = dots_for_row(a1, b1, w0a, w0b, w1a, w1b);
        float2 d2 = dots_for_row(a2, b2, w0a, w0b, w1a, w1b);
        float2 d3 = dots_for_row(a3, b3, w0a, w0b, w1a, w1b);

        #pragma unroll
        for (int off = 16; off > 0; off >>= 1) {
            d0.x += __shfl_xor_sync(0xffffffff, d0.x, off);
            d0.y += __shfl_xor_sync(0xffffffff, d0.y, off);
            d1.x += __shfl_xor_sync(0xffffffff, d1.x, off);
            d1.y += __shfl_xor_sync(0xffffffff, d1.y, off);
            d2.x += __shfl_xor_sync(0xffffffff, d2.x, off);
            d2.y += __shfl_xor_sync(0xffffffff, d2.y, off);
            d3.x += __shfl_xor_sync(0xffffffff, d3.x, off);
            d3.y += __shfl_xor_sync(0xffffffff, d3.y, off);
        }

        if (lane == 0) {
            float s0 = group_term(c0, d0.x, y0[v])  + group_term(c1, d0.y, y1[v]);
            float s1 = group_term(c0, d1.x, y0[v1]) + group_term(c1, d1.y, y1[v1]);
            float s2 = group_term(c0, d2.x, y0[v2]) + group_term(c1, d2.y, y1[v2]);
            float s3 = group_term(c0, d3.x, y0[v3]) + group_term(c1, d3.y, y1[v3]);
            acc += (double)(s0 + s1) + (double)(s2 + s3);
        }
    }
    // remainder, one voxel at a time
    for (; v < V; v += step) {
        const float4* x0 = (const float4*)(X + (size_t)v * SDIM);
        float4 a0 = __ldcs(x0 + lane), b0 = __ldcs(x0 + lane + 32);
        float2 d0 = dots_for_row(a0, b0, w0a, w0b, w1a, w1b);
        #pragma unroll
        for (int off = 16; off > 0; off >>= 1) {
            d0.x += __shfl_xor_sync(0xffffffff, d0.x, off);
            d0.y += __shfl_xor_sync(0xffffffff, d0.y, off);
        }
        if (lane == 0)
            acc += (double)(group_term(c0, d0.x, y0[v]) + group_term(c1, d0.y, y1[v]));
    }

    __shared__ double sred[8];
    if (lane == 0) sred[widb] = acc;
    __syncthreads();
    if (threadIdx.x == 0) {
        double t = 0.0;
        for (int i = 0; i < nwb; ++i) t += sred[i];
        atomicAdd(&g_sum, t);
    }
}

__global__ void finalize_kernel(float* out)
{
    out[0] = (float)(-g_sum);
}

extern "C" void kernel_launch(void* const* d_in, const int* in_sizes, int n_in,
                              void* d_out, int out_size)
{
    const float* X    = (const float*)d_in[0]; // [V,256]
    const float* mod0 = (const float*)d_in[1]; // [S,64]
    const float* mod1 = (const float*)d_in[2];
    const float* y0   = (const float*)d_in[3]; // [V,1]
    const float* y1   = (const float*)d_in[4];
    const float* W    = (const float*)d_in[5]; // [2,256]
    const float* wm   = (const float*)d_in[6]; // [1,64]
    const float* ods  = (const float*)d_in[7]; // [2]
    float* out = (float*)d_out;

    const int V = in_sizes[0] / SDIM;
    const int S = in_sizes[1] / MDIM;

    setup_kernel<<<1, 1024>>>(mod0, mod1, wm, ods, S);
    nb_main_kernel<<<1184, 256>>>(X, y0, y1, W, V);
    finalize_kernel<<<1, 1>>>(out);
}

// round 3
// speedup vs baseline: 1.6793x; 1.2374x over previous
#include <cuda_runtime.h>
#include <math.h>

#define SDIM   256
#define MDIM   64

// Per-group precomputed constants
struct GConst {
    float k;      // sum_m2 / (v*sum_m)
    float logk;
    float r;      // v*sum_m^2/sum_m2 (per-group scalar)
    float T1, T2, T3; // lgamma(y+r)-lgamma(y+1)-lgamma(r) for y=1,2,3
};

__device__ GConst g_c[2];
__device__ double g_sum;
// Partial accumulators for setup: {sum_m g0, sum_m2 g0, sum_m g1, sum_m2 g1}.
// Zero-initialized at module load; setup_finalize resets them to 0 after
// consuming, so every graph replay sees zeros. Deterministic.
__device__ double g_acc[4] = {0.0, 0.0, 0.0, 0.0};

// ---------------------------------------------------------------------------
// Kernel 0a: moderator partial sums, multi-block. 64 blocks x 256 threads.
// ---------------------------------------------------------------------------
__global__ void __launch_bounds__(256)
setup_partial_kernel(const float* __restrict__ mod0,
                     const float* __restrict__ mod1,
                     const float* __restrict__ wm,
                     int nstudy)
{
    __shared__ float swm[MDIM];
    const int tid = threadIdx.x;
    if (tid < MDIM) swm[tid] = wm[tid];
    __syncthreads();

    const int gid     = blockIdx.x * blockDim.x + tid;
    const int gstride = gridDim.x * blockDim.x;

    double m0 = 0.0, m20 = 0.0, m1 = 0.0, m21 = 0.0;
    for (int s = gid; s < nstudy; s += gstride) {
        const float4* r0 = (const float4*)(mod0 + (size_t)s * MDIM);
        const float4* r1 = (const float4*)(mod1 + (size_t)s * MDIM);
        float d0 = 0.f, d1 = 0.f;
        #pragma unroll
        for (int j = 0; j < MDIM / 4; ++j) {
            float4 a = r0[j], b = r1[j];
            const float4 w = ((const float4*)swm)[j];
            d0 += a.x*w.x + a.y*w.y + a.z*w.z + a.w*w.w;
            d1 += b.x*w.x + b.y*w.y + b.z*w.z + b.w*w.w;
        }
        float e0 = expf(d0), e1 = expf(d1);
        m0  += (double)e0;  m20 += (double)e0 * (double)e0;
        m1  += (double)e1;  m21 += (double)e1 * (double)e1;
    }

    // warp reduce, then one atomic per value per warp (few hundred total)
    #pragma unroll
    for (int off = 16; off > 0; off >>= 1) {
        m0  += __shfl_xor_sync(0xffffffff, m0,  off);
        m20 += __shfl_xor_sync(0xffffffff, m20, off);
        m1  += __shfl_xor_sync(0xffffffff, m1,  off);
        m21 += __shfl_xor_sync(0xffffffff, m21, off);
    }
    if ((tid & 31) == 0) {
        atomicAdd(&g_acc[0], m0);
        atomicAdd(&g_acc[1], m20);
        atomicAdd(&g_acc[2], m1);
        atomicAdd(&g_acc[3], m21);
    }
}

// ---------------------------------------------------------------------------
// Kernel 0b: finalize constants (1 thread), then reset accumulators so the
// next graph replay starts from zero.
// ---------------------------------------------------------------------------
__global__ void setup_finalize_kernel(const float* __restrict__ ods)
{
    double sm[2]  = {g_acc[0], g_acc[2]};
    double sm2[2] = {g_acc[1], g_acc[3]};
    #pragma unroll
    for (int g = 0; g < 2; ++g) {
        float  s  = ods[g];
        double v  = 1.0 / ((double)s * (double)s);
        double r  = v * sm[g] * sm[g] / sm2[g];
        double k  = sm2[g] / (v * sm[g]);
        float rf = (float)r;
        float T1 = logf(rf);
        float T2 = T1 + logf(rf + 1.0f) - 0.6931471805599453f;   // -log2
        float T3 = T2 + logf(rf + 2.0f) - 1.0986122886681098f;   // -log3
        g_c[g].k = (float)k;
        g_c[g].logk = logf((float)k);
        g_c[g].r = rf;
        g_c[g].T1 = T1;
        g_c[g].T2 = T2;
        g_c[g].T3 = T3;
    }
    g_sum = 0.0;
    g_acc[0] = 0.0; g_acc[1] = 0.0; g_acc[2] = 0.0; g_acc[3] = 0.0;
}

// term = -(r+y)*log1p(t) + y*(dot + logk) + T[y],  t = k*exp(dot)
__device__ __forceinline__ float group_term(const GConst gc, float dot, float y)
{
    float t  = gc.k * __expf(dot);
    float l1 = log1pf(t);
    int iy = (int)y;
    float T = (iy == 1) ? gc.T1 : (iy == 2) ? gc.T2 : (iy == 3) ? gc.T3 : 0.0f;
    return fmaf(-(gc.r + y), l1, fmaf(y, gc.logk + dot, T));
}

__device__ __forceinline__ float2 dots_for_row(const float4 a, const float4 b,
                                               const float4 w0a, const float4 w0b,
                                               const float4 w1a, const float4 w1b)
{
    float p0 = a.x*w0a.x + a.y*w0a.y + a.z*w0a.z + a.w*w0a.w
             + b.x*w0b.x + b.y*w0b.y + b.z*w0b.z + b.w*w0b.w;
    float p1 = a.x*w1a.x + a.y*w1a.y + a.z*w1a.z + a.w*w1a.w
             + b.x*w1b.x + b.y*w1b.y + b.z*w1b.z + b.w*w1b.w;
    return make_float2(p0, p1);
}

// ---------------------------------------------------------------------------
// Kernel 1: streaming kernel. Warp per voxel, 4x unroll, __ldcs streaming.
// (unchanged from R2 for clean attribution)
// ---------------------------------------------------------------------------
__global__ void __launch_bounds__(256)
nb_main_kernel(const float* __restrict__ X,
               const float* __restrict__ y0,
               const float* __restrict__ y1,
               const float* __restrict__ W,
               int V)
{
    const int lane   = threadIdx.x & 31;
    const int widb   = threadIdx.x >> 5;
    const int nwb    = blockDim.x >> 5;
    const int gwarp  = blockIdx.x * nwb + widb;
    const int nwarps = gridDim.x * nwb;

    const float4* W4 = (const float4*)W;
    const float4 w0a = W4[lane],      w0b = W4[lane + 32];
    const float4 w1a = W4[64 + lane], w1b = W4[96 + lane];

    const GConst c0 = g_c[0];
    const GConst c1 = g_c[1];

    double acc = 0.0;

    int v = gwarp;
    const int step = nwarps;
    for (; v + 3 * step < V; v += 4 * step) {
        const int v1 = v + step, v2 = v + 2 * step, v3 = v + 3 * step;
        const float4* x0 = (const float4*)(X + (size_t)v  * SDIM);
        const float4* x1 = (const float4*)(X + (size_t)v1 * SDIM);
        const float4* x2 = (const float4*)(X + (size_t)v2 * SDIM);
        const float4* x3 = (const float4*)(X + (size_t)v3 * SDIM);

        float4 a0 = __ldcs(x0 + lane), b0 = __ldcs(x0 + lane + 32);
        float4 a1 = __ldcs(x1 + lane), b1 = __ldcs(x1 + lane + 32);
        float4 a2 = __ldcs(x2 + lane), b2 = __ldcs(x2 + lane + 32);
        float4 a3 = __ldcs(x3 + lane), b3 = __ldcs(x3 + lane + 32);

        float2 d0 = dots_for_row(a0, b0, w0a, w0b, w1a, w1b);
        float2 d1 = dots_for_row(a1, b1, w0a, w0b, w1a, w1b);
        float2 d2 = dots_for_row(a2, b2, w0a, w0b, w1a, w1b);
        float2 d3 = dots_for_row(a3, b3, w0a, w0b, w1a, w1b);

        #pragma unroll
        for (int off = 16; off > 0; off >>= 1) {
            d0.x += __shfl_xor_sync(0xffffffff, d0.x, off);
            d0.y += __shfl_xor_sync(0xffffffff, d0.y, off);
            d1.x += __shfl_xor_sync(0xffffffff, d1.x, off);
            d1.y += __shfl_xor_sync(0xffffffff, d1.y, off);
            d2.x += __shfl_xor_sync(0xffffffff, d2.x, off);
            d2.y += __shfl_xor_sync(0xffffffff, d2.y, off);
            d3.x += __shfl_xor_sync(0xffffffff, d3.x, off);
            d3.y += __shfl_xor_sync(0xffffffff, d3.y, off);
        }

        if (lane == 0) {
            float s0 = group_term(c0, d0.x, y0[v])  + group_term(c1, d0.y, y1[v]);
            float s1 = group_term(c0, d1.x, y0[v1]) + group_term(c1, d1.y, y1[v1]);
            float s2 = group_term(c0, d2.x, y0[v2]) + group_term(c1, d2.y, y1[v2]);
            float s3 = group_term(c0, d3.x, y0[v3]) + group_term(c1, d3.y, y1[v3]);
            acc += (double)(s0 + s1) + (double)(s2 + s3);
        }
    }
    for (; v < V; v += step) {
        const float4* x0 = (const float4*)(X + (size_t)v * SDIM);
        float4 a0 = __ldcs(x0 + lane), b0 = __ldcs(x0 + lane + 32);
        float2 d0 = dots_for_row(a0, b0, w0a, w0b, w1a, w1b);
        #pragma unroll
        for (int off = 16; off > 0; off >>= 1) {
            d0.x += __shfl_xor_sync(0xffffffff, d0.x, off);
            d0.y += __shfl_xor_sync(0xffffffff, d0.y, off);
        }
        if (lane == 0)
            acc += (double)(group_term(c0, d0.x, y0[v]) + group_term(c1, d0.y, y1[v]));
    }

    __shared__ double sred[8];
    if (lane == 0) sred[widb] = acc;
    __syncthreads();
    if (threadIdx.x == 0) {
        double t = 0.0;
        for (int i = 0; i < nwb; ++i) t += sred[i];
        atomicAdd(&g_sum, t);
    }
}

__global__ void finalize_kernel(float* out)
{
    out[0] = (float)(-g_sum);
}

extern "C" void kernel_launch(void* const* d_in, const int* in_sizes, int n_in,
                              void* d_out, int out_size)
{
    const float* X    = (const float*)d_in[0]; // [V,256]
    const float* mod0 = (const float*)d_in[1]; // [S,64]
    const float* mod1 = (const float*)d_in[2];
    const float* y0   = (const float*)d_in[3]; // [V,1]
    const float* y1   = (const float*)d_in[4];
    const float* W    = (const float*)d_in[5]; // [2,256]
    const float* wm   = (const float*)d_in[6]; // [1,64]
    const float* ods  = (const float*)d_in[7]; // [2]
    float* out = (float*)d_out;

    const int V = in_sizes[0] / SDIM;
    const int S = in_sizes[1] / MDIM;

    setup_partial_kernel<<<64, 256>>>(mod0, mod1, wm, S);
    setup_finalize_kernel<<<1, 1>>>(ods);
    nb_main_kernel<<<1184, 256>>>(X, y0, y1, W, V);
    finalize_kernel<<<1, 1>>>(out);
}

// round 4
// speedup vs baseline: 2.1174x; 1.2609x over previous
#include <cuda_runtime.h>
#include <math.h>

#define SDIM   256
#define MDIM   64

// Per-group precomputed constants
struct GConst {
    float k;      // sum_m2 / (v*sum_m)
    float logk;
    float r;      // v*sum_m^2/sum_m2 (per-group scalar)
    float T1, T2, T3; // lgamma(y+r)-lgamma(y+1)-lgamma(r) for y=1,2,3
};

__device__ GConst g_c[2];
__device__ double g_sum = 0.0;
// {sum_m g0, sum_m2 g0, sum_m g1, sum_m2 g1}; reset by consumer each replay.
__device__ double g_acc[4] = {0.0, 0.0, 0.0, 0.0};
__device__ unsigned g_tick0 = 0;   // setup last-block ticket
__device__ unsigned g_tick1 = 0;   // main  last-block ticket

// ---------------------------------------------------------------------------
// Kernel 0: moderator sums + in-kernel finalize (last block). 8 blocks x 128.
// ---------------------------------------------------------------------------
__global__ void __launch_bounds__(128)
setup_kernel(const float* __restrict__ mod0,
             const float* __restrict__ mod1,
             const float* __restrict__ wm,
             const float* __restrict__ ods,
             int nstudy)
{
    __shared__ float swm[MDIM];
    const int tid = threadIdx.x;
    if (tid < MDIM) swm[tid] = wm[tid];
    __syncthreads();

    const int gid     = blockIdx.x * blockDim.x + tid;
    const int gstride = gridDim.x * blockDim.x;

    double m0 = 0.0, m20 = 0.0, m1 = 0.0, m21 = 0.0;
    for (int s = gid; s < nstudy; s += gstride) {
        const float4* r0 = (const float4*)(mod0 + (size_t)s * MDIM);
        const float4* r1 = (const float4*)(mod1 + (size_t)s * MDIM);
        float d0 = 0.f, d1 = 0.f;
        #pragma unroll
        for (int j = 0; j < MDIM / 4; ++j) {
            float4 a = r0[j], b = r1[j];
            const float4 w = ((const float4*)swm)[j];
            d0 += a.x*w.x + a.y*w.y + a.z*w.z + a.w*w.w;
            d1 += b.x*w.x + b.y*w.y + b.z*w.z + b.w*w.w;
        }
        float e0 = expf(d0), e1 = expf(d1);
        m0  += (double)e0;  m20 += (double)e0 * (double)e0;
        m1  += (double)e1;  m21 += (double)e1 * (double)e1;
    }

    #pragma unroll
    for (int off = 16; off > 0; off >>= 1) {
        m0  += __shfl_xor_sync(0xffffffff, m0,  off);
        m20 += __shfl_xor_sync(0xffffffff, m20, off);
        m1  += __shfl_xor_sync(0xffffffff, m1,  off);
        m21 += __shfl_xor_sync(0xffffffff, m21, off);
    }
    if ((tid & 31) == 0) {
        atomicAdd(&g_acc[0], m0);
        atomicAdd(&g_acc[1], m20);
        atomicAdd(&g_acc[2], m1);
        atomicAdd(&g_acc[3], m21);
    }
    __threadfence();
    __syncthreads();

    if (tid == 0) {
        unsigned t = atomicAdd(&g_tick0, 1u);
        if (t == gridDim.x - 1) {
            __threadfence();
            double sm[2], sm2[2];
            sm[0]  = atomicAdd(&g_acc[0], 0.0);
            sm2[0] = atomicAdd(&g_acc[1], 0.0);
            sm[1]  = atomicAdd(&g_acc[2], 0.0);
            sm2[1] = atomicAdd(&g_acc[3], 0.0);
            #pragma unroll
            for (int g = 0; g < 2; ++g) {
                float  s  = ods[g];
                double v  = 1.0 / ((double)s * (double)s);
                double r  = v * sm[g] * sm[g] / sm2[g];
                double k  = sm2[g] / (v * sm[g]);
                float rf = (float)r;
                float T1 = logf(rf);
                float T2 = T1 + logf(rf + 1.0f) - 0.6931471805599453f;
                float T3 = T2 + logf(rf + 2.0f) - 1.0986122886681098f;
                g_c[g].k = (float)k;
                g_c[g].logk = logf((float)k);
                g_c[g].r = rf;
                g_c[g].T1 = T1;
                g_c[g].T2 = T2;
                g_c[g].T3 = T3;
            }
            g_sum = 0.0;
            g_acc[0] = 0.0; g_acc[1] = 0.0; g_acc[2] = 0.0; g_acc[3] = 0.0;
            g_tick0 = 0;
            __threadfence();
        }
    }
}

// term = -(r+y)*log1p(t) + y*(dot + logk) + T[y],  t = k*exp(dot)
__device__ __forceinline__ float group_term(float k, float logk, float r,
                                            float T1, float T2, float T3,
                                            float dot, float y)
{
    float t  = k * __expf(dot);
    float l1 = log1pf(t);
    int iy = (int)y;
    float T = (iy == 1) ? T1 : (iy == 2) ? T2 : (iy == 3) ? T3 : 0.0f;
    return fmaf(-(r + y), l1, fmaf(y, logk + dot, T));
}

__device__ __forceinline__ float2 dots_for_row(const float4 a, const float4 b,
                                               const float4 w0a, const float4 w0b,
                                               const float4 w1a, const float4 w1b)
{
    float p0 = a.x*w0a.x + a.y*w0a.y + a.z*w0a.z + a.w*w0a.w
             + b.x*w0b.x + b.y*w0b.y + b.z*w0b.z + b.w*w0b.w;
    float p1 = a.x*w1a.x + a.y*w1a.y + a.z*w1a.z + a.w*w1a.w
             + b.x*w1b.x + b.y*w1b.y + b.z*w1b.z + b.w*w1b.w;
    return make_float2(p0, p1);
}

// ---------------------------------------------------------------------------
// Kernel 1: streaming. Warp handles CONTIGUOUS groups of 4 voxels.
// Epilogue distributed over lanes 0-7. Last block writes the output.
// ---------------------------------------------------------------------------
__global__ void __launch_bounds__(256, 3)
nb_main_kernel(const float* __restrict__ X,
               const float* __restrict__ y0,
               const float* __restrict__ y1,
               const float* __restrict__ W,
               float* __restrict__ out,
               int V)
{
    const int lane   = threadIdx.x & 31;
    const int widb   = threadIdx.x >> 5;
    const int nwb    = blockDim.x >> 5;
    const int gwarp  = blockIdx.x * nwb + widb;
    const int nwarps = gridDim.x * nwb;

    const float4* W4 = (const float4*)W;
    const float4 w0a = W4[lane],      w0b = W4[lane + 32];
    const float4 w1a = W4[64 + lane], w1b = W4[96 + lane];

    const GConst c0 = g_c[0];
    const GConst c1 = g_c[1];
    // Per-lane group constants: odd lanes -> group 1, even -> group 0
    const bool odd = (lane & 1);
    const float sk    = odd ? c1.k    : c0.k;
    const float slogk = odd ? c1.logk : c0.logk;
    const float sr    = odd ? c1.r    : c0.r;
    const float sT1   = odd ? c1.T1   : c0.T1;
    const float sT2   = odd ? c1.T2   : c0.T2;
    const float sT3   = odd ? c1.T3   : c0.T3;

    double acc = 0.0;

    const int ngroups = (V + 3) >> 2;   // groups of 4 contiguous voxels
    for (int g = gwarp; g < ngroups; g += nwarps) {
        const int v = g << 2;
        const float4* xr = (const float4*)(X + (size_t)v * SDIM);

        // 4 contiguous rows: 4KB contiguous block, fully coalesced
        float4 a0 = __ldcs(xr + lane),       b0 = __ldcs(xr + lane + 32);
        float4 a1 = __ldcs(xr + lane + 64),  b1 = __ldcs(xr + lane + 96);
        float4 a2 = __ldcs(xr + lane + 128), b2 = __ldcs(xr + lane + 160);
        float4 a3 = __ldcs(xr + lane + 192), b3 = __ldcs(xr + lane + 224);

        // y for this iteration: lanes 0-7, (voxel = v + lane/2, group = lane&1)
        float ylv = 0.f;
        if (lane < 8) {
            const float* yp = odd ? y1 : y0;
            int idx = v + (lane >> 1);
            if (idx < V) ylv = yp[idx];
        }

        float2 d0 = dots_for_row(a0, b0, w0a, w0b, w1a, w1b);
        float2 d1 = dots_for_row(a1, b1, w0a, w0b, w1a, w1b);
        float2 d2 = dots_for_row(a2, b2, w0a, w0b, w1a, w1b);
        float2 d3 = dots_for_row(a3, b3, w0a, w0b, w1a, w1b);

        #pragma unroll
        for (int off = 16; off > 0; off >>= 1) {
            d0.x += __shfl_xor_sync(0xffffffff, d0.x, off);
            d0.y += __shfl_xor_sync(0xffffffff, d0.y, off);
            d1.x += __shfl_xor_sync(0xffffffff, d1.x, off);
            d1.y += __shfl_xor_sync(0xffffffff, d1.y, off);
            d2.x += __shfl_xor_sync(0xffffffff, d2.x, off);
            d2.y += __shfl_xor_sync(0xffffffff, d2.y, off);
            d3.x += __shfl_xor_sync(0xffffffff, d3.x, off);
            d3.y += __shfl_xor_sync(0xffffffff, d3.y, off);
        }

        // lane i (0-7) picks value i: voxel (i>>1), group (i&1)
        float2 dj = d0;
        const int q = (lane >> 1) & 3;
        if (q == 1) dj = d1;
        if (q == 2) dj = d2;
        if (q == 3) dj = d3;
        const float dot = odd ? dj.y : dj.x;

        float term = 0.f;
        if (lane < 8 && (v + (lane >> 1)) < V)
            term = group_term(sk, slogk, sr, sT1, sT2, sT3, dot, ylv);

        term += __shfl_xor_sync(0xffffffff, term, 1);
        term += __shfl_xor_sync(0xffffffff, term, 2);
        term += __shfl_xor_sync(0xffffffff, term, 4);
        if (lane == 0) acc += (double)term;
    }

    // block reduce, one atomic per block, last block writes output
    __shared__ double sred[8];
    if (lane == 0) sred[widb] = acc;
    __syncthreads();
    if (threadIdx.x == 0) {
        double t = 0.0;
        for (int i = 0; i < nwb; ++i) t += sred[i];
        atomicAdd(&g_sum, t);
        __threadfence();
        unsigned tk = atomicAdd(&g_tick1, 1u);
        if (tk == gridDim.x - 1) {
            __threadfence();
            double total = atomicAdd(&g_sum, 0.0);
            out[0] = (float)(-total);
            g_tick1 = 0;
            __threadfence();
        }
    }
}

extern "C" void kernel_launch(void* const* d_in, const int* in_sizes, int n_in,
                              void* d_out, int out_size)
{
    const float* X    = (const float*)d_in[0]; // [V,256]
    const float* mod0 = (const float*)d_in[1]; // [S,64]
    const float* mod1 = (const float*)d_in[2];
    const float* y0   = (const float*)d_in[3]; // [V,1]
    const float* y1   = (const float*)d_in[4];
    const float* W    = (const float*)d_in[5]; // [2,256]
    const float* wm   = (const float*)d_in[6]; // [1,64]
    const float* ods  = (const float*)d_in[7]; // [2]
    float* out = (float*)d_out;

    const int V = in_sizes[0] / SDIM;
    const int S = in_sizes[1] / MDIM;

    setup_kernel<<<8, 128>>>(mod0, mod1, wm, ods, S);
    nb_main_kernel<<<1184, 256>>>(X, y0, y1, W, out, V);
}

// round 5
// speedup vs baseline: 2.2264x; 1.0515x over previous
#include <cuda_runtime.h>
#include <math.h>

#define SDIM   256
#define MDIM   64

struct GConst {
    float k, logk, r, T1, T2, T3;
};

__device__ GConst g_c[2];
__device__ double g_sum = 0.0;
__device__ double g_acc[4] = {0.0, 0.0, 0.0, 0.0};
__device__ unsigned g_tick0 = 0;
__device__ unsigned g_tick1 = 0;

// ---------------------------------------------------------------------------
// Kernel 0: moderator sums + in-kernel finalize (last block). 8 blocks x 128.
// ---------------------------------------------------------------------------
__global__ void __launch_bounds__(128)
setup_kernel(const float* __restrict__ mod0,
             const float* __restrict__ mod1,
             const float* __restrict__ wm,
             const float* __restrict__ ods,
             int nstudy)
{
    __shared__ float swm[MDIM];
    const int tid = threadIdx.x;
    if (tid < MDIM) swm[tid] = wm[tid];
    __syncthreads();

    const int gid     = blockIdx.x * blockDim.x + tid;
    const int gstride = gridDim.x * blockDim.x;

    double m0 = 0.0, m20 = 0.0, m1 = 0.0, m21 = 0.0;
    for (int s = gid; s < nstudy; s += gstride) {
        const float4* r0 = (const float4*)(mod0 + (size_t)s * MDIM);
        const float4* r1 = (const float4*)(mod1 + (size_t)s * MDIM);
        float d0 = 0.f, d1 = 0.f;
        #pragma unroll
        for (int j = 0; j < MDIM / 4; ++j) {
            float4 a = r0[j], b = r1[j];
            const float4 w = ((const float4*)swm)[j];
            d0 += a.x*w.x + a.y*w.y + a.z*w.z + a.w*w.w;
            d1 += b.x*w.x + b.y*w.y + b.z*w.z + b.w*w.w;
        }
        float e0 = expf(d0), e1 = expf(d1);
        m0  += (double)e0;  m20 += (double)e0 * (double)e0;
        m1  += (double)e1;  m21 += (double)e1 * (double)e1;
    }

    #pragma unroll
    for (int off = 16; off > 0; off >>= 1) {
        m0  += __shfl_xor_sync(0xffffffff, m0,  off);
        m20 += __shfl_xor_sync(0xffffffff, m20, off);
        m1  += __shfl_xor_sync(0xffffffff, m1,  off);
        m21 += __shfl_xor_sync(0xffffffff, m21, off);
    }
    if ((tid & 31) == 0) {
        atomicAdd(&g_acc[0], m0);
        atomicAdd(&g_acc[1], m20);
        atomicAdd(&g_acc[2], m1);
        atomicAdd(&g_acc[3], m21);
    }
    __threadfence();
    __syncthreads();

    if (tid == 0) {
        unsigned t = atomicAdd(&g_tick0, 1u);
        if (t == gridDim.x - 1) {
            __threadfence();
            double sm[2], sm2[2];
            sm[0]  = atomicAdd(&g_acc[0], 0.0);
            sm2[0] = atomicAdd(&g_acc[1], 0.0);
            sm[1]  = atomicAdd(&g_acc[2], 0.0);
            sm2[1] = atomicAdd(&g_acc[3], 0.0);
            #pragma unroll
            for (int g = 0; g < 2; ++g) {
                float  s  = ods[g];
                double v  = 1.0 / ((double)s * (double)s);
                double r  = v * sm[g] * sm[g] / sm2[g];
                double k  = sm2[g] / (v * sm[g]);
                float rf = (float)r;
                float T1 = logf(rf);
                float T2 = T1 + logf(rf + 1.0f) - 0.6931471805599453f;
                float T3 = T2 + logf(rf + 2.0f) - 1.0986122886681098f;
                g_c[g].k = (float)k;
                g_c[g].logk = logf((float)k);
                g_c[g].r = rf;
                g_c[g].T1 = T1;
                g_c[g].T2 = T2;
                g_c[g].T3 = T3;
            }
            g_sum = 0.0;
            g_acc[0] = 0.0; g_acc[1] = 0.0; g_acc[2] = 0.0; g_acc[3] = 0.0;
            g_tick0 = 0;
            __threadfence();
        }
    }
}

__device__ __forceinline__ float group_term(float k, float logk, float r,
                                            float T1, float T2, float T3,
                                            float dot, float y)
{
    float t  = k * __expf(dot);
    float l1 = log1pf(t);
    int iy = (int)y;
    float T = (iy == 1) ? T1 : (iy == 2) ? T2 : (iy == 3) ? T3 : 0.0f;
    return fmaf(-(r + y), l1, fmaf(y, logk + dot, T));
}

__device__ __forceinline__ float2 dots_for_row(const float4 a, const float4 b,
                                               const float4 w0a, const float4 w0b,
                                               const float4 w1a, const float4 w1b)
{
    float p0 = a.x*w0a.x + a.y*w0a.y + a.z*w0a.z + a.w*w0a.w
             + b.x*w0b.x + b.y*w0b.y + b.z*w0b.z + b.w*w0b.w;
    float p1 = a.x*w1a.x + a.y*w1a.y + a.z*w1a.z + a.w*w1a.w
             + b.x*w1b.x + b.y*w1b.y + b.z*w1b.z + b.w*w1b.w;
    return make_float2(p0, p1);
}

// Merge two per-lane values across the 'o' butterfly: after this, lanes with
// bit o clear hold A+A(partner), lanes with bit o set hold B+B(partner).
__device__ __forceinline__ float merge_pair(float A, float B, int o)
{
    float send = (threadIdx.x & o) ? A : B;
    float keep = (threadIdx.x & o) ? B : A;
    return keep + __shfl_xor_sync(0xffffffff, send, o);
}

// ---------------------------------------------------------------------------
// Kernel 1: streaming. Warp handles contiguous groups of 4 voxels.
// Multi-value merge reduction (9 SHFL), distributed epilogue (lanes 0-7).
// ---------------------------------------------------------------------------
__global__ void __launch_bounds__(256, 4)
nb_main_kernel(const float* __restrict__ X,
               const float* __restrict__ y0,
               const float* __restrict__ y1,
               const float* __restrict__ W,
               float* __restrict__ out,
               int V)
{
    const int lane   = threadIdx.x & 31;
    const int widb   = threadIdx.x >> 5;
    const int nwb    = blockDim.x >> 5;
    const int gwarp  = blockIdx.x * nwb + widb;
    const int nwarps = gridDim.x * nwb;

    const float4* W4 = (const float4*)W;
    const float4 w0a = W4[lane],      w0b = W4[lane + 32];
    const float4 w1a = W4[64 + lane], w1b = W4[96 + lane];

    const GConst c0 = g_c[0];
    const GConst c1 = g_c[1];
    // lane mapping for epilogue: group = lane&1, row = (lane>>1)&3
    const bool odd = (lane & 1);
    const float sk    = odd ? c1.k    : c0.k;
    const float slogk = odd ? c1.logk : c0.logk;
    const float sr    = odd ? c1.r    : c0.r;
    const float sT1   = odd ? c1.T1   : c0.T1;
    const float sT2   = odd ? c1.T2   : c0.T2;
    const float sT3   = odd ? c1.T3   : c0.T3;
    const float* yp   = odd ? y1 : y0;

    double acc = 0.0;

    const int ngroups = (V + 3) >> 2;
    for (int g = gwarp; g < ngroups; g += nwarps) {
        const int v = g << 2;
        // clamp row indices for a possible partial tail group (terms gated later)
        const int r1 = min(v + 1, V - 1);
        const int r2 = min(v + 2, V - 1);
        const int r3 = min(v + 3, V - 1);
        const float4* x0 = (const float4*)(X + (size_t)v  * SDIM);
        const float4* x1 = (const float4*)(X + (size_t)r1 * SDIM);
        const float4* x2 = (const float4*)(X + (size_t)r2 * SDIM);
        const float4* x3 = (const float4*)(X + (size_t)r3 * SDIM);

        float4 a0 = __ldcs(x0 + lane), b0 = __ldcs(x0 + lane + 32);
        float4 a1 = __ldcs(x1 + lane), b1 = __ldcs(x1 + lane + 32);
        float4 a2 = __ldcs(x2 + lane), b2 = __ldcs(x2 + lane + 32);
        float4 a3 = __ldcs(x3 + lane), b3 = __ldcs(x3 + lane + 32);

        // y for this group: lanes 0-7 (voxel = v + (lane>>1), group = lane&1)
        float ylv = 0.f;
        if (lane < 8) {
            int idx = v + (lane >> 1);
            if (idx < V) ylv = __ldcs(yp + idx);
        }

        float2 d0 = dots_for_row(a0, b0, w0a, w0b, w1a, w1b);
        float2 d1 = dots_for_row(a1, b1, w0a, w0b, w1a, w1b);
        float2 d2 = dots_for_row(a2, b2, w0a, w0b, w1a, w1b);
        float2 d3 = dots_for_row(a3, b3, w0a, w0b, w1a, w1b);

        // multi-value reduction: 8 values -> per-lane slot in 9 shuffles.
        // offset 1: group split (bit0: clear->x/g0, set->y/g1)
        float e0 = merge_pair(d0.x, d0.y, 1);
        float e1 = merge_pair(d1.x, d1.y, 1);
        float e2 = merge_pair(d2.x, d2.y, 1);
        float e3 = merge_pair(d3.x, d3.y, 1);
        // offset 2: row bit0 (bit1: clear->row0/2, set->row1/3)
        float f0 = merge_pair(e0, e1, 2);
        float f1 = merge_pair(e2, e3, 2);
        // offset 4: row bit1 (bit2: clear->rows01, set->rows23)
        float gg = merge_pair(f0, f1, 4);
        // fold the remaining lane redundancy
        gg += __shfl_xor_sync(0xffffffff, gg, 8);
        gg += __shfl_xor_sync(0xffffffff, gg, 16);
        // now lane l holds dot(voxel v+((l>>1)&3), group l&1), full 32-lane sum

        float term = 0.f;
        if (lane < 8 && (v + (lane >> 1)) < V)
            term = group_term(sk, slogk, sr, sT1, sT2, sT3, gg, ylv);

        term += __shfl_xor_sync(0xffffffff, term, 1);
        term += __shfl_xor_sync(0xffffffff, term, 2);
        term += __shfl_xor_sync(0xffffffff, term, 4);
        if (lane == 0) acc += (double)term;
    }

    __shared__ double sred[8];
    if (lane == 0) sred[widb] = acc;
    __syncthreads();
    if (threadIdx.x == 0) {
        double t = 0.0;
        for (int i = 0; i < nwb; ++i) t += sred[i];
        atomicAdd(&g_sum, t);
        __threadfence();
        unsigned tk = atomicAdd(&g_tick1, 1u);
        if (tk == gridDim.x - 1) {
            __threadfence();
            double total = atomicAdd(&g_sum, 0.0);
            out[0] = (float)(-total);
            g_tick1 = 0;
            __threadfence();
        }
    }
}

extern "C" void kernel_launch(void* const* d_in, const int* in_sizes, int n_in,
                              void* d_out, int out_size)
{
    const float* X    = (const float*)d_in[0];
    const float* mod0 = (const float*)d_in[1];
    const float* mod1 = (const float*)d_in[2];
    const float* y0   = (const float*)d_in[3];
    const float* y1   = (const float*)d_in[4];
    const float* W    = (const float*)d_in[5];
    const float* wm   = (const float*)d_in[6];
    const float* ods  = (const float*)d_in[7];
    float* out = (float*)d_out;

    const int V = in_sizes[0] / SDIM;
    const int S = in_sizes[1] / MDIM;

    setup_kernel<<<8, 128>>>(mod0, mod1, wm, ods, S);
    nb_main_kernel<<<1184, 256>>>(X, y0, y1, W, out, V);
}